// round 2
// baseline (speedup 1.0000x reference)
#include <cuda_runtime.h>
#include <cstdint>
#include <cstdio>

#define BB   16
#define NN   2048
#define FINN 64
#define FOUT 32
#define KK   16
#define RR   16
#define EPSF 1e-8f

// noise = -log(-log(q+eps)) >= -log(-log(eps)) = -2.91347...  -> lq >= s - 2.9135
#define NOISE_MARGIN 2.9145f

#define H_ELEMS   (BB*NN*FOUT)      /* 1048576 */
#define BNK       (BB*NN*KK)        /* 524288  */

__device__ float g_sq[BB*NN];

static __device__ __forceinline__ unsigned long long ffma2(unsigned long long a,
                                                           unsigned long long b,
                                                           unsigned long long c){
    unsigned long long d;
    asm("fma.rn.f32x2 %0, %1, %2, %3;" : "=l"(d) : "l"(a), "l"(b), "l"(c));
    return d;
}

static __device__ __forceinline__ float finf(){ return __int_as_float(0x7f800000); }

static __device__ __forceinline__ bool lessvi(float v1, int j1, float v2, int j2){
    return (v1 < v2) || (v1 == v2 && j1 < j2);
}

// sorted-ascending insert into register-resident (tv,tj)[KK]
static __device__ __forceinline__ void insert16(float v, int j, float tv[KK], int tj[KK]){
    if (lessvi(v, j, tv[KK-1], tj[KK-1])){
        tv[KK-1] = v; tj[KK-1] = j;
        #pragma unroll
        for (int k2 = KK-1; k2 > 0; --k2){
            float av = tv[k2-1], bv = tv[k2];
            int   aj = tj[k2-1], bj = tj[k2];
            bool sw = lessvi(bv, bj, av, aj);
            tv[k2-1] = sw ? bv : av; tj[k2-1] = sw ? bj : aj;
            tv[k2]   = sw ? av : bv; tj[k2]   = sw ? aj : bj;
        }
    }
}

// warp-cooperative merge of 32 sorted-per-lane top-16 lists -> ascending 16 in pV/pJ
static __device__ __forceinline__ void warp_merge16(int lane, float tv[KK], int tj[KK],
                                                    float* dV, int* dJ,
                                                    float* pV, int* pJ){
    #pragma unroll
    for (int k2 = 0; k2 < KK; ++k2){ dV[lane*KK+k2] = tv[k2]; dJ[lane*KK+k2] = tj[k2]; }
    __syncwarp();
    int p = 1;
    float hv = tv[0]; int hj = tj[0];
    for (int tt = 0; tt < KK; ++tt){
        float bv = hv; int bj = hj;
        #pragma unroll
        for (int o = 16; o; o >>= 1){
            float ov = __shfl_down_sync(0xffffffffu, bv, o);
            int   oj = __shfl_down_sync(0xffffffffu, bj, o);
            if (lessvi(ov, oj, bv, bj)){ bv = ov; bj = oj; }
        }
        bv = __shfl_sync(0xffffffffu, bv, 0);
        bj = __shfl_sync(0xffffffffu, bj, 0);
        if (lane == 0){ pV[tt] = bv; pJ[tt] = bj; }
        if (hv == bv && hj == bj){
            hv = (p < KK) ? dV[lane*KK+p] : finf();
            hj = (p < KK) ? dJ[lane*KK+p] : 0x7fffffff;
            ++p;
        }
    }
    __syncwarp();
}

// ---------------- kernel 1: h = x@W, sq = rowwise ||h||^2 ----------------
__global__ void k_embed(const float* __restrict__ x, const float* __restrict__ W,
                        float* __restrict__ hout){
    __shared__ float Ws[FINN*FOUT];
    __shared__ float xs[8][FINN];
    int t = threadIdx.x;
    for (int i = t; i < FINN*FOUT; i += 256) Ws[i] = W[i];
    int row0 = blockIdx.x * 8;
    for (int i = t; i < 8*FINN; i += 256){
        int r = i / FINN, f = i % FINN;
        xs[r][f] = x[(size_t)(row0 + r)*FINN + f];
    }
    __syncthreads();
    int r = t >> 5, d = t & 31;
    float acc = 0.f;
    #pragma unroll
    for (int f = 0; f < FINN; ++f)
        acc = fmaf(xs[r][f], Ws[f*FOUT + d], acc);
    int row = row0 + r;
    hout[(size_t)row*FOUT + d] = acc;
    float v = acc * acc;
    #pragma unroll
    for (int o = 16; o; o >>= 1) v += __shfl_xor_sync(0xffffffffu, v, o);
    if (d == 0) g_sq[row] = v;
}

// ---------------- kernel 2: scores + pruned exact gumbel top-k ----------------
__global__ __launch_bounds__(256, 1)
void k_rows(const float* __restrict__ h, const float* __restrict__ q,
            const float* __restrict__ temp,
            float* __restrict__ e0, float* __restrict__ lp){
    extern __shared__ float sm[];
    float* sS  = sm;                    // RR*NN score row cache
    float* hi  = sm + RR*NN;            // RR*FOUT
    float* sqi = hi + RR*FOUT;          // RR
    __shared__ float dumpV[8][32*KK];
    __shared__ int   dumpJ[8][32*KK];
    __shared__ float probeV[8][KK];
    __shared__ int   probeJ[8][KK];

    const int t  = threadIdx.x;
    const int b  = blockIdx.x / (NN/RR);
    const int i0 = (blockIdx.x % (NN/RR)) * RR;
    const float* hb = h + (size_t)b*NN*FOUT;

    for (int i = t; i < RR*FOUT; i += 256) hi[i] = hb[(size_t)i0*FOUT + i];
    if (t < RR) sqi[t] = g_sq[b*NN + i0 + t];
    const float ET = expf(fminf(fmaxf(temp[0], -5.f), 5.f));
    __syncthreads();

    // ---- gram phase: s[i][j] = ET * max(sq_i + sq_j - 2 h_i.h_j, 0) ----
    for (int jt = 0; jt < NN; jt += 512){
        int j0 = jt + t, j1 = j0 + 256;
        unsigned long long a0[16], a1[16];
        const ulonglong2* p0 = reinterpret_cast<const ulonglong2*>(hb + (size_t)j0*FOUT);
        const ulonglong2* p1 = reinterpret_cast<const ulonglong2*>(hb + (size_t)j1*FOUT);
        #pragma unroll
        for (int u = 0; u < 8; ++u){           // FIX: 8 x 16B = full 128B row (was 4)
            ulonglong2 v0 = p0[u]; a0[2*u] = v0.x; a0[2*u+1] = v0.y;
            ulonglong2 v1 = p1[u]; a1[2*u] = v1.x; a1[2*u+1] = v1.y;
        }
        float sq0 = g_sq[b*NN + j0], sq1 = g_sq[b*NN + j1];
        #pragma unroll
        for (int i = 0; i < RR; ++i){
            unsigned long long acc0 = 0ull, acc1 = 0ull;
            const unsigned long long* wi =
                reinterpret_cast<const unsigned long long*>(hi + i*FOUT);
            #pragma unroll
            for (int dp = 0; dp < 16; ++dp){
                unsigned long long w = wi[dp];
                acc0 = ffma2(a0[dp], w, acc0);
                acc1 = ffma2(a1[dp], w, acc1);
            }
            float2 f0 = *reinterpret_cast<float2*>(&acc0);
            float2 f1 = *reinterpret_cast<float2*>(&acc1);
            float dot0 = f0.x + f0.y, dot1 = f1.x + f1.y;
            float s0 = fmaxf(sqi[i] + sq0 - 2.f*dot0, 0.f) * ET;
            float s1 = fmaxf(sqi[i] + sq1 - 2.f*dot1, 0.f) * ET;
            sS[i*NN + j0] = s0;
            sS[i*NN + j1] = s1;
        }
    }
    __syncthreads();

    // ---- selection phase: one warp per row ----
    const int warp = t >> 5, lane = t & 31;
    float* dV = dumpV[warp]; int* dJ = dumpJ[warp];
    float* pV = probeV[warp]; int* pJ = probeJ[warp];

    for (int ii = warp; ii < RR; ii += 8){
        const int n = i0 + ii;
        const float* srow = sS + ii*NN;
        const float* qrow = q + ((size_t)b*NN + n)*NN;

        // 1) per-lane sorted top-16 of noise-free scores
        float tv[KK]; int tj[KK];
        #pragma unroll
        for (int k2 = 0; k2 < KK; ++k2){ tv[k2] = finf(); tj[k2] = 0x7fffffff; }
        for (int m = 0; m < NN/32; ++m){
            int j = lane + 32*m;
            insert16(srow[j], j, tv, tj);
        }
        warp_merge16(lane, tv, tj, dV, dJ, pV, pJ);

        // 2) probe those 16 with their true gumbel value -> threshold T
        float myLq = -finf();
        if (lane < KK){
            int j = pJ[lane];
            float qv = qrow[j];
            myLq = pV[lane] - logf(-logf(qv + EPSF));
        }
        float T = myLq;
        #pragma unroll
        for (int o = 16; o; o >>= 1) T = fmaxf(T, __shfl_xor_sync(0xffffffffu, T, o));
        const float thresh = T + NOISE_MARGIN;   // provably contains the true top-16

        // 3) exact rescan of candidates only
        #pragma unroll
        for (int k2 = 0; k2 < KK; ++k2){ tv[k2] = finf(); tj[k2] = 0x7fffffff; }
        for (int m = 0; m < NN/32; ++m){
            int j = lane + 32*m;
            float s = srow[j];
            if (s <= thresh){
                float qv = qrow[j];
                float lq = s - logf(-logf(qv + EPSF));
                insert16(lq, j, tv, tj);
            }
        }
        warp_merge16(lane, tv, tj, dV, dJ, pV, pJ);

        // 4) emit: logprobs = -lq (descending), edges with per-graph offset
        if (lane < KK){
            float lqv = pV[lane]; int j = pJ[lane];
            size_t base = ((size_t)b*NN + n)*KK + lane;
            lp[base] = -lqv;
            e0[base] = (float)(j + b*NN);
            e0[base + BNK] = (float)(n + b*NN);
        }
        __syncwarp();
    }
}

extern "C" void kernel_launch(void* const* d_in, const int* in_sizes, int n_in,
                              void* d_out, int out_size){
    const float* x    = (const float*)d_in[0];
    const float* W    = (const float*)d_in[1];
    const float* temp = (const float*)d_in[2];
    const float* q    = (const float*)d_in[3];
    float* out  = (float*)d_out;
    float* hout = out;                 // [B,N,Fout]
    float* e0   = out + H_ELEMS;       // [2, B*N*K] (row0 then row1)
    float* lp   = out + H_ELEMS + 2*BNK; // [B,N,K]

    k_embed<<<BB*NN/8, 256>>>(x, W, hout);

    const int smem2 = (RR*NN + RR*FOUT + RR) * (int)sizeof(float);
    cudaFuncSetAttribute(k_rows, cudaFuncAttributeMaxDynamicSharedMemorySize, smem2);
    k_rows<<<BB*NN/RR, 256, smem2>>>(hout, q, temp, e0, lp);
}

// round 3
// speedup vs baseline: 2.5323x; 2.5323x over previous
#include <cuda_runtime.h>
#include <cstdint>

#define BB   16
#define NN   2048
#define FINN 64
#define FOUT 32
#define KK   16
#define RR   16
#define TPB  512
#define EPSF 1e-8f

// noise = log(-log(q+eps)) <= log(-log(eps)) = 2.91347...  -> lq >= s - 2.9135
#define NOISE_MARGIN 2.9145f

#define H_ELEMS   (BB*NN*FOUT)      /* 1048576 */
#define BNK       (BB*NN*KK)        /* 524288  */

__device__ float g_sq[BB*NN];

static __device__ __forceinline__ unsigned long long ffma2(unsigned long long a,
                                                           unsigned long long b,
                                                           unsigned long long c){
    unsigned long long d;
    asm("fma.rn.f32x2 %0, %1, %2, %3;" : "=l"(d) : "l"(a), "l"(b), "l"(c));
    return d;
}

static __device__ __forceinline__ float finf(){ return __int_as_float(0x7f800000); }

static __device__ __forceinline__ bool lessvi(float v1, int j1, float v2, int j2){
    return (v1 < v2) || (v1 == v2 && j1 < j2);
}

// full bitonic sort of 32 (v,j) pairs across the warp, ascending by (v, j)
static __device__ __forceinline__ void bsort32(int lane, float& v, int& j){
    #pragma unroll
    for (int k = 2; k <= 32; k <<= 1){
        #pragma unroll
        for (int s = k >> 1; s > 0; s >>= 1){
            float ov = __shfl_xor_sync(0xffffffffu, v, s);
            int   oj = __shfl_xor_sync(0xffffffffu, j, s);
            bool up      = ((lane & k) == 0);
            bool lower   = ((lane & s) == 0);
            bool takeMin = (up == lower);
            bool oless   = lessvi(ov, oj, v, j);
            if (takeMin ? oless : !oless){ v = ov; j = oj; }
        }
    }
}

static __device__ __forceinline__ float gumbel_lq(float s, float qv){
    return s - logf(-logf(qv + EPSF));
}

// ---------------- kernel 1: h = x@W, sq = rowwise ||h||^2 ----------------
__global__ void k_embed(const float* __restrict__ x, const float* __restrict__ W,
                        float* __restrict__ hout){
    __shared__ float Ws[FINN*FOUT];
    __shared__ float xs[8][FINN];
    int t = threadIdx.x;
    for (int i = t; i < FINN*FOUT; i += 256) Ws[i] = W[i];
    int row0 = blockIdx.x * 8;
    for (int i = t; i < 8*FINN; i += 256){
        int r = i / FINN, f = i % FINN;
        xs[r][f] = x[(size_t)(row0 + r)*FINN + f];
    }
    __syncthreads();
    int r = t >> 5, d = t & 31;
    float acc = 0.f;
    #pragma unroll
    for (int f = 0; f < FINN; ++f)
        acc = fmaf(xs[r][f], Ws[f*FOUT + d], acc);
    int row = row0 + r;
    hout[(size_t)row*FOUT + d] = acc;
    float v = acc * acc;
    #pragma unroll
    for (int o = 16; o; o >>= 1) v += __shfl_xor_sync(0xffffffffu, v, o);
    if (d == 0) g_sq[row] = v;
}

// ---------------- kernel 2: scores + pruned exact gumbel top-k ----------------
__global__ __launch_bounds__(TPB, 1)
void k_rows(const float* __restrict__ h, const float* __restrict__ q,
            const float* __restrict__ temp,
            float* __restrict__ e0, float* __restrict__ lp){
    extern __shared__ float sm[];
    float* sS  = sm;                    // RR*NN score row cache
    float* hi  = sm + RR*NN;            // RR*FOUT
    float* sqi = hi + RR*FOUT;          // RR
    __shared__ float stageS[RR][48];
    __shared__ int   stageJ[RR][48];

    const int t  = threadIdx.x;
    const int b  = blockIdx.x / (NN/RR);
    const int i0 = (blockIdx.x % (NN/RR)) * RR;
    const float* hb = h + (size_t)b*NN*FOUT;

    for (int i = t; i < RR*FOUT; i += TPB) hi[i] = hb[(size_t)i0*FOUT + i];
    if (t < RR) sqi[t] = g_sq[b*NN + i0 + t];
    const float ET = expf(fminf(fmaxf(temp[0], -5.f), 5.f));
    __syncthreads();

    // ---- gram phase: s[i][j] = ET * max(sq_i + sq_j - 2 h_i.h_j, 0) ----
    #pragma unroll
    for (int jt = 0; jt < NN; jt += 2*TPB){
        int j0 = jt + t, j1 = j0 + TPB;
        unsigned long long a0[16], a1[16];
        const ulonglong2* p0 = reinterpret_cast<const ulonglong2*>(hb + (size_t)j0*FOUT);
        const ulonglong2* p1 = reinterpret_cast<const ulonglong2*>(hb + (size_t)j1*FOUT);
        #pragma unroll
        for (int u = 0; u < 8; ++u){
            ulonglong2 v0 = p0[u]; a0[2*u] = v0.x; a0[2*u+1] = v0.y;
            ulonglong2 v1 = p1[u]; a1[2*u] = v1.x; a1[2*u+1] = v1.y;
        }
        float sq0 = g_sq[b*NN + j0], sq1 = g_sq[b*NN + j1];
        #pragma unroll
        for (int i = 0; i < RR; ++i){
            unsigned long long acc0 = 0ull, acc1 = 0ull;
            const unsigned long long* wi =
                reinterpret_cast<const unsigned long long*>(hi + i*FOUT);
            #pragma unroll
            for (int dp = 0; dp < 16; ++dp){
                unsigned long long w = wi[dp];
                acc0 = ffma2(a0[dp], w, acc0);
                acc1 = ffma2(a1[dp], w, acc1);
            }
            float2 f0 = *reinterpret_cast<float2*>(&acc0);
            float2 f1 = *reinterpret_cast<float2*>(&acc1);
            float dot0 = f0.x + f0.y, dot1 = f1.x + f1.y;
            sS[i*NN + j0] = fmaxf(sqi[i] + sq0 - 2.f*dot0, 0.f) * ET;
            sS[i*NN + j1] = fmaxf(sqi[i] + sq1 - 2.f*dot1, 0.f) * ET;
        }
    }
    __syncthreads();

    // ---- selection phase: one warp per row ----
    const int warp = t >> 5, lane = t & 31;
    const int n = i0 + warp;
    const float* srow = sS + warp*NN;
    const float* qrow = q + ((size_t)b*NN + n)*NN;
    float* stS = stageS[warp];
    int*   stJ = stageJ[warp];

    // 1) per-lane min over its 64 strided values
    float mv = finf(); int mj = 0x7fffffff;
    #pragma unroll 8
    for (int m = 0; m < NN/32; ++m){
        int j = lane + 32*m;
        float s = srow[j];
        if (lessvi(s, j, mv, mj)){ mv = s; mj = j; }
    }

    // 2) probe each lane-min with its true gumbel value; T = 16th smallest
    float pv = gumbel_lq(mv, qrow[mj]);
    int   pj = mj;
    bsort32(lane, pv, pj);
    const float T = __shfl_sync(0xffffffffu, pv, 15);
    const float thresh = T + NOISE_MARGIN;   // provably contains the true top-16

    // 3) exact scan: ballot-compact candidates, chunked merge with best-16
    float bv = finf(); int bj = 0x7fffffff;  // best-16 lives in lanes 0..15
    int cnt = 0;
    for (int m = 0; m < NN/32; ++m){
        int j = lane + 32*m;
        float s = srow[j];
        bool c = (s <= thresh);
        unsigned mask = __ballot_sync(0xffffffffu, c);
        if (mask){
            int pos = __popc(mask & ((1u << lane) - 1u));
            if (c){ stS[cnt + pos] = s; stJ[cnt + pos] = j; }
            cnt += __popc(mask);
            __syncwarp();
            if (cnt >= 16){
                // merge stage[0..15] into best-16
                float v = bv; int jj = bj;
                if (lane >= 16){
                    int idx = lane - 16;
                    float ss = stS[idx]; int sj = stJ[idx];
                    v = gumbel_lq(ss, qrow[sj]); jj = sj;
                }
                bsort32(lane, v, jj);
                bv = v; bj = jj;
                // shift remaining stage entries down
                int rem = cnt - 16;
                float tv_ = 0.f; int tj_ = 0;
                if (lane < rem){ tv_ = stS[16 + lane]; tj_ = stJ[16 + lane]; }
                __syncwarp();
                if (lane < rem){ stS[lane] = tv_; stJ[lane] = tj_; }
                __syncwarp();
                cnt = rem;
            }
        }
    }
    if (cnt > 0){   // final partial merge
        float v = bv; int jj = bj;
        if (lane >= 16){
            int idx = lane - 16;
            if (idx < cnt){
                float ss = stS[idx]; int sj = stJ[idx];
                v = gumbel_lq(ss, qrow[sj]); jj = sj;
            } else { v = finf(); jj = 0x7fffffff; }
        }
        bsort32(lane, v, jj);
        bv = v; bj = jj;
    }

    // 4) emit: logprobs = -lq (descending), edges with per-graph offset
    if (lane < KK){
        size_t base = ((size_t)b*NN + n)*KK + lane;
        lp[base] = -bv;
        e0[base] = (float)(bj + b*NN);
        e0[base + BNK] = (float)(n + b*NN);
    }
}

extern "C" void kernel_launch(void* const* d_in, const int* in_sizes, int n_in,
                              void* d_out, int out_size){
    const float* x    = (const float*)d_in[0];
    const float* W    = (const float*)d_in[1];
    const float* temp = (const float*)d_in[2];
    const float* q    = (const float*)d_in[3];
    float* out  = (float*)d_out;
    float* hout = out;                   // [B,N,Fout]
    float* e0   = out + H_ELEMS;         // [2, B*N*K]
    float* lp   = out + H_ELEMS + 2*BNK; // [B,N,K]

    k_embed<<<BB*NN/8, 256>>>(x, W, hout);

    const int smem2 = (RR*NN + RR*FOUT + RR) * (int)sizeof(float);
    cudaFuncSetAttribute(k_rows, cudaFuncAttributeMaxDynamicSharedMemorySize, smem2);
    k_rows<<<BB*NN/RR, TPB, smem2>>>(hout, q, temp, e0, lp);
}

// round 5
// speedup vs baseline: 6.7667x; 2.6721x over previous
#include <cuda_runtime.h>
#include <cstdint>

#define BB   16
#define NN   2048
#define FINN 64
#define FOUT 32
#define KK   16
#define RR   16
#define TPB  512
#define SR   1024            /* rows per h stage */
#define HSTRIDE 33           /* padded floats per staged row */
#define EPSF 1e-8f
#define NOISE_MARGIN 2.9150f /* -log(-log(eps)) = -2.91347 */

#define H_ELEMS   (BB*NN*FOUT)
#define BNK       (BB*NN*KK)

__device__ float g_sq[BB*NN];

typedef unsigned long long ull;

static __device__ __forceinline__ ull ffma2(ull a, ull b, ull c){
    ull d;
    asm("fma.rn.f32x2 %0, %1, %2, %3;" : "=l"(d) : "l"(a), "l"(b), "l"(c));
    return d;
}
static __device__ __forceinline__ ull packf2(float lo, float hi){
    ull r;
    asm("mov.b64 %0, {%1, %2};" : "=l"(r) : "r"(__float_as_uint(lo)), "r"(__float_as_uint(hi)));
    return r;
}
static __device__ __forceinline__ float2 unpackf2(ull v){
    float2 f; uint32_t lo, hi;
    asm("mov.b64 {%0, %1}, %2;" : "=r"(lo), "=r"(hi) : "l"(v));
    f.x = __uint_as_float(lo); f.y = __uint_as_float(hi);
    return f;
}
static __device__ __forceinline__ float finf(){ return __int_as_float(0x7f800000); }
static __device__ __forceinline__ bool lessvi(float v1, int j1, float v2, int j2){
    return (v1 < v2) || (v1 == v2 && j1 < j2);
}
// warp bitonic sort of 32 (v,j), ascending by (v,j)
static __device__ __forceinline__ void bsort32(int lane, float& v, int& j){
    #pragma unroll
    for (int k = 2; k <= 32; k <<= 1){
        #pragma unroll
        for (int s = k >> 1; s > 0; s >>= 1){
            float ov = __shfl_xor_sync(0xffffffffu, v, s);
            int   oj = __shfl_xor_sync(0xffffffffu, j, s);
            bool takeMin = (((lane & k) == 0) == ((lane & s) == 0));
            bool oless   = lessvi(ov, oj, v, j);
            if (takeMin ? oless : !oless){ v = ov; j = oj; }
        }
    }
}
static __device__ __forceinline__ float gumbel_lq(float s, float qv){
    return s - logf(-logf(qv + EPSF));
}

// ---------------- kernel 1: h = x@W, sq = ||h_row||^2 ----------------
__global__ void k_embed(const float* __restrict__ x, const float* __restrict__ W,
                        float* __restrict__ hout){
    __shared__ float Ws[FINN*FOUT];
    __shared__ float xs[8][FINN];
    int t = threadIdx.x;
    for (int i = t; i < FINN*FOUT; i += 256) Ws[i] = W[i];
    int row0 = blockIdx.x * 8;
    for (int i = t; i < 8*FINN; i += 256){
        int r = i / FINN, f = i % FINN;
        xs[r][f] = x[(size_t)(row0 + r)*FINN + f];
    }
    __syncthreads();
    int r = t >> 5, d = t & 31;
    float acc = 0.f;
    #pragma unroll
    for (int f = 0; f < FINN; ++f)
        acc = fmaf(xs[r][f], Ws[f*FOUT + d], acc);
    int row = row0 + r;
    hout[(size_t)row*FOUT + d] = acc;
    float v = acc * acc;
    #pragma unroll
    for (int o = 16; o; o >>= 1) v += __shfl_xor_sync(0xffffffffu, v, o);
    if (d == 0) g_sq[row] = v;
}

// ---------------- kernel 2: gram (bf16 cache) + pruned exact gumbel top-k ----------------
__global__ __launch_bounds__(TPB, 1)
void k_rows(const float* __restrict__ h, const float* __restrict__ q,
            const float* __restrict__ temp,
            float* __restrict__ e0, float* __restrict__ lp){
    extern __shared__ float sm[];
    uint32_t* sSu  = (uint32_t*)sm;          // RR * 1024 packed bf16x2 scores (64 KB)
    float* hstage  = sm + RR*(NN/2);         // SR * HSTRIDE floats (132 KB)
    float* hi      = hstage + SR*HSTRIDE;    // RR * FOUT
    float* sqi     = hi + RR*FOUT;           // RR
    __shared__ int stJ[RR][96];

    const int t  = threadIdx.x;
    const int b  = blockIdx.x / (NN/RR);
    const int i0 = (blockIdx.x % (NN/RR)) * RR;
    const float* hb = h + (size_t)b*NN*FOUT;

    for (int i = t; i < RR*FOUT; i += TPB) hi[i] = hb[(size_t)i0*FOUT + i];
    if (t < RR) sqi[t] = g_sq[b*NN + i0 + t];
    const float ET = expf(fminf(fmaxf(temp[0], -5.f), 5.f));
    __syncthreads();

    // ---- gram phase: 2 stages of 1024 rows ----
    for (int st = 0; st < 2; ++st){
        const int j_base = st * SR;
        // coalesced copy h[j_base .. j_base+SR) -> padded smem stage
        for (int g = t; g < SR*8; g += TPB){
            int r = g >> 3, c = (g & 7) * 4;
            float4 v = *reinterpret_cast<const float4*>(hb + (size_t)(j_base + r)*FOUT + c);
            float* dst = hstage + r*HSTRIDE + c;
            dst[0] = v.x; dst[1] = v.y; dst[2] = v.z; dst[3] = v.w;
        }
        __syncthreads();

        // this thread's two adjacent rows
        const float* pL = hstage + (2*t    )*HSTRIDE;
        const float* pH = hstage + (2*t + 1)*HSTRIDE;
        ull aL[16], aH[16];
        #pragma unroll
        for (int d2 = 0; d2 < 16; ++d2){
            aL[d2] = packf2(pL[2*d2], pL[2*d2+1]);
            aH[d2] = packf2(pH[2*d2], pH[2*d2+1]);
        }
        const int jL = j_base + 2*t, jH = jL + 1;
        const float sqL = g_sq[b*NN + jL], sqH = g_sq[b*NN + jH];

        #pragma unroll
        for (int i = 0; i < RR; ++i){
            ull acc0 = 0ull, acc1 = 0ull;
            const ull* wi = reinterpret_cast<const ull*>(hi + i*FOUT);
            #pragma unroll
            for (int dp = 0; dp < 16; ++dp){
                ull w = wi[dp];
                acc0 = ffma2(aL[dp], w, acc0);
                acc1 = ffma2(aH[dp], w, acc1);
            }
            float2 f0 = unpackf2(acc0), f1 = unpackf2(acc1);
            float s0 = fmaxf(sqi[i] + sqL - 2.f*(f0.x + f0.y), 0.f) * ET;
            float s1 = fmaxf(sqi[i] + sqH - 2.f*(f1.x + f1.y), 0.f) * ET;
            uint32_t pk;
            asm("cvt.rn.satfinite.bf16x2.f32 %0, %1, %2;" : "=r"(pk) : "f"(s1), "f"(s0));
            sSu[i*(NN/2) + (j_base >> 1) + t] = pk;
        }
        __syncthreads();
    }

    // ---- selection: one warp per row ----
    const int warp = t >> 5, lane = t & 31;
    const int n = i0 + warp;
    const uint32_t* srowu = sSu + warp*(NN/2);
    const float* qrow = q + ((size_t)b*NN + n)*NN;
    const ull* wi = reinterpret_cast<const ull*>(hi + warp*FOUT);
    const float sqI = sqi[warp];
    int* stage = stJ[warp];
    const unsigned lmask = (1u << lane) - 1u;

    // 1) per-lane min via packed integer keys (s_bf16 << 11 | j)
    uint32_t kE = 0xffffffffu, kO = 0xffffffffu;
    #pragma unroll 8
    for (int m = 0; m < 32; ++m){
        uint32_t wIdx = (uint32_t)(lane + 32*m);
        uint32_t w = srowu[wIdx];
        uint32_t k0 = ((w & 0xffffu) << 11) | (2u*wIdx);
        uint32_t k1 = ((w >> 16)    << 11) | (2u*wIdx + 1u);
        kE = min(kE, k0); kO = min(kO, k1);
    }
    uint32_t kmin = min(kE, kO);

    // 2) probe the 32 lane-mins -> valid threshold T (16th smallest probed lq~)
    {
        int jp = (int)(kmin & 2047u);
        float sp = __uint_as_float((kmin >> 11) << 16);
        float pv = gumbel_lq(sp, qrow[jp]);
        int pj = jp;
        bsort32(lane, pv, pj);
        float T = __shfl_sync(0xffffffffu, pv, 15);
        // conservative bf16-space bound (covers probe + scan rounding)
        float bf = fmaxf(T + NOISE_MARGIN, 0.f) * 1.0157f;
        uint32_t ub = (__float_as_uint(bf) + 0xffffu) >> 16;

        // 3) scan: ballot-compact candidate indices; exact merge in batches of 16
        float bv = finf(); int bj = 0x7fffffff;
        int cnt = 0;
        for (int m = 0; m < 32; ++m){
            uint32_t wIdx = (uint32_t)(lane + 32*m);
            uint32_t w = srowu[wIdx];
            bool c0 = (w & 0xffffu) <= ub;
            bool c1 = (w >> 16)     <= ub;
            unsigned m0 = __ballot_sync(0xffffffffu, c0);
            unsigned m1 = __ballot_sync(0xffffffffu, c1);
            if (m0 | m1){
                int n0 = __popc(m0);
                if (c0) stage[cnt + __popc(m0 & lmask)] = 2*(int)wIdx;
                if (c1) stage[cnt + n0 + __popc(m1 & lmask)] = 2*(int)wIdx + 1;
                cnt += n0 + __popc(m1);
                __syncwarp();
                while (cnt >= 16){
                    float v = bv; int jj = bj;
                    if (lane >= 16){
                        int j = stage[cnt - 16 + (lane - 16)];
                        const ull* aj = reinterpret_cast<const ull*>(hb + (size_t)j*FOUT);
                        ull acc = 0ull;
                        #pragma unroll
                        for (int dp = 0; dp < 16; ++dp) acc = ffma2(aj[dp], wi[dp], acc);
                        float2 f = unpackf2(acc);
                        float s = fmaxf(sqI + g_sq[b*NN + j] - 2.f*(f.x + f.y), 0.f) * ET;
                        v = gumbel_lq(s, qrow[j]); jj = j;
                    }
                    bsort32(lane, v, jj);
                    bv = v; bj = jj;
                    cnt -= 16;
                }
            }
        }
        if (cnt > 0){
            float v = bv; int jj = bj;
            if (lane >= 16){
                int idx = lane - 16;
                if (idx < cnt){
                    int j = stage[idx];
                    const ull* aj = reinterpret_cast<const ull*>(hb + (size_t)j*FOUT);
                    ull acc = 0ull;
                    #pragma unroll
                    for (int dp = 0; dp < 16; ++dp) acc = ffma2(aj[dp], wi[dp], acc);
                    float2 f = unpackf2(acc);
                    float s = fmaxf(sqI + g_sq[b*NN + j] - 2.f*(f.x + f.y), 0.f) * ET;
                    v = gumbel_lq(s, qrow[j]); jj = j;
                } else { v = finf(); jj = 0x7fffffff; }
            }
            bsort32(lane, v, jj);
            bv = v; bj = jj;
        }

        // 4) emit
        if (lane < KK){
            size_t base = ((size_t)b*NN + n)*KK + lane;
            lp[base] = -bv;
            e0[base] = (float)(bj + b*NN);
            e0[base + BNK] = (float)(n + b*NN);
        }
    }
}

extern "C" void kernel_launch(void* const* d_in, const int* in_sizes, int n_in,
                              void* d_out, int out_size){
    const float* x    = (const float*)d_in[0];
    const float* W    = (const float*)d_in[1];
    const float* temp = (const float*)d_in[2];
    const float* q    = (const float*)d_in[3];
    float* out  = (float*)d_out;
    float* hout = out;                   // [B,N,Fout]
    float* e0   = out + H_ELEMS;         // [2, B*N*K]
    float* lp   = out + H_ELEMS + 2*BNK; // [B,N,K]

    k_embed<<<BB*NN/8, 256>>>(x, W, hout);

    const int smem2 = (RR*(NN/2) + SR*HSTRIDE + RR*FOUT + RR) * (int)sizeof(float);
    cudaFuncSetAttribute(k_rows, cudaFuncAttributeMaxDynamicSharedMemorySize, smem2);
    k_rows<<<BB*NN/RR, TPB, smem2>>>(hout, q, temp, e0, lp);
}